// round 2
// baseline (speedup 1.0000x reference)
#include <cuda_runtime.h>
#include <math.h>

#define BB 2
#define LL 1024
#define DD 768
#define HH 12
#define DHH 64
#define DP 32
#define MLPD 3072
#define NLAYER 4
#define WIN 128
#define BW 264           // padded window-bias row stride (257 used)
#define EPS_RMS 1.1920929e-07f
#define EPS_LN 1e-5f

// ---------------- scratch (static device allocations) ----------------
__device__ float g_h[BB * LL * DD];
__device__ float g_qkv[BB * LL * 3 * DD];
__device__ float g_q[BB * HH * LL * DHH];
__device__ float g_k[BB * HH * LL * DHH];
__device__ float g_v[BB * HH * LL * DHH];
__device__ float g_y[BB * LL * DD];
__device__ float g_u[BB * LL * MLPD];
__device__ float g_bias[NLAYER * BB * LL * BW];

// ---------------- helpers ----------------
__device__ __forceinline__ float warp_sum(float v) {
#pragma unroll
    for (int o = 16; o; o >>= 1) v += __shfl_xor_sync(0xffffffffu, v, o);
    return v;
}

__device__ __forceinline__ float gelu_f(float x) {
    return 0.5f * x * (1.0f + erff(x * 0.70710678118654752f));
}

// ---------------- pair-bias (all layers, windowed) ----------------
__global__ void bias_kernel(const float* __restrict__ pair,
                            const float* __restrict__ ln_g, const float* __restrict__ ln_b,
                            const float* __restrict__ pb_w, const float* __restrict__ pb_b,
                            float* __restrict__ bout) {
    const int WN = 2 * WIN + 1;  // 257
    int gw = (blockIdx.x * blockDim.x + threadIdx.x) >> 5;
    int lane = threadIdx.x & 31;
    int total = BB * LL * WN;
    if (gw >= total) return;
    int w = gw % WN;
    int t = gw / WN;
    int qq = t % LL;
    int b = t / LL;
    int j = qq - WIN + w;
    if (j < 0 || j >= LL) return;

    float x = pair[(((size_t)b * LL + qq) * LL + j) * DP + lane];
    float m = warp_sum(x) * (1.0f / 32.0f);
    float d = x - m;
    float var = warp_sum(d * d) * (1.0f / 32.0f);
    float nm = d * rsqrtf(var + EPS_LN);
#pragma unroll
    for (int l = 0; l < NLAYER; l++) {
        float wv = pb_w[l * DP + lane];
        float contrib = (nm * ln_g[l * DP + lane] + ln_b[l * DP + lane]) * wv;
        float sum = warp_sum(contrib);
        if (lane == 0)
            bout[(((size_t)l * BB + b) * LL + qq) * BW + w] = sum + pb_b[l];
    }
}

// ---------------- rmsnorm ----------------
__global__ void rmsnorm_kernel(const float* __restrict__ s, float* __restrict__ h) {
    __shared__ float red[8];
    __shared__ float s_inv;
    int row = blockIdx.x;
    int tid = threadIdx.x;
    const float* x = s + (size_t)row * DD;
    float v0 = x[tid], v1 = x[tid + 256], v2 = x[tid + 512];
    float ss = v0 * v0 + v1 * v1 + v2 * v2;
    ss = warp_sum(ss);
    if ((tid & 31) == 0) red[tid >> 5] = ss;
    __syncthreads();
    if (tid == 0) {
        float t = 0.f;
#pragma unroll
        for (int i = 0; i < 8; i++) t += red[i];
        s_inv = rsqrtf(t * (1.0f / (float)DD) + EPS_RMS);
    }
    __syncthreads();
    float inv = s_inv;
    float* ho = h + (size_t)row * DD;
    ho[tid] = v0 * inv; ho[tid + 256] = v1 * inv; ho[tid + 512] = v2 * inv;
}

// ---------------- generic SGEMM: out[N,M] = A[N,K] @ W[M,K]^T + bias ----------------
// ACT: 0=none 1=gelu ; RESID: out += result
template <int ACT, int RESID>
__global__ void gemm_kernel(const float* __restrict__ A, const float* __restrict__ W,
                            const float* __restrict__ bias, float* __restrict__ out,
                            int K, int M) {
    constexpr int BM = 128, BN = 64, BK = 16;
    __shared__ __align__(16) float As[BK][BM];
    __shared__ __align__(16) float Ws[BK][BN];
    const int tid = threadIdx.x;
    const int tx = tid & 15;
    const int ty = tid >> 4;
    const int row0 = blockIdx.y * BM;
    const int col0 = blockIdx.x * BN;
    const int lrow = tid >> 2;       // 0..63
    const int lk = (tid & 3) * 4;    // k offset within BK

    const float* Aptr = A + (size_t)(row0 + lrow) * K + lk;
    const float* A2ptr = Aptr + (size_t)64 * K;
    const float* Wptr = W + (size_t)(col0 + lrow) * K + lk;

    float acc[8][4];
#pragma unroll
    for (int i = 0; i < 8; i++)
#pragma unroll
        for (int j = 0; j < 4; j++) acc[i][j] = 0.f;

    for (int k0 = 0; k0 < K; k0 += BK) {
        float4 a0 = *(const float4*)(Aptr + k0);
        float4 a1 = *(const float4*)(A2ptr + k0);
        float4 w0 = *(const float4*)(Wptr + k0);
        As[lk + 0][lrow] = a0.x; As[lk + 1][lrow] = a0.y;
        As[lk + 2][lrow] = a0.z; As[lk + 3][lrow] = a0.w;
        As[lk + 0][lrow + 64] = a1.x; As[lk + 1][lrow + 64] = a1.y;
        As[lk + 2][lrow + 64] = a1.z; As[lk + 3][lrow + 64] = a1.w;
        Ws[lk + 0][lrow] = w0.x; Ws[lk + 1][lrow] = w0.y;
        Ws[lk + 2][lrow] = w0.z; Ws[lk + 3][lrow] = w0.w;
        __syncthreads();
#pragma unroll
        for (int kk = 0; kk < BK; kk++) {
            float4 t0 = *(const float4*)&As[kk][ty * 8];
            float4 t1 = *(const float4*)&As[kk][ty * 8 + 4];
            float4 tw = *(const float4*)&Ws[kk][tx * 4];
            float a[8] = {t0.x, t0.y, t0.z, t0.w, t1.x, t1.y, t1.z, t1.w};
            float w[4] = {tw.x, tw.y, tw.z, tw.w};
#pragma unroll
            for (int i = 0; i < 8; i++)
#pragma unroll
                for (int j = 0; j < 4; j++) acc[i][j] = fmaf(a[i], w[j], acc[i][j]);
        }
        __syncthreads();
    }
#pragma unroll
    for (int i = 0; i < 8; i++) {
        int r = row0 + ty * 8 + i;
        float* orow = out + (size_t)r * M + col0 + tx * 4;
        const float* brow = bias + col0 + tx * 4;
#pragma unroll
        for (int j = 0; j < 4; j++) {
            float vv = acc[i][j] + brow[j];
            if (ACT == 1) vv = gelu_f(vv);
            if (RESID) vv += orow[j];
            orow[j] = vv;
        }
    }
}

// ---------------- RoPE + layout change [B,L,3D] -> q,k,v [B,H,L,DH] ----------------
__global__ void rope_kernel(const float* __restrict__ qkv, float* __restrict__ qo,
                            float* __restrict__ ko, float* __restrict__ vo) {
    int idx = blockIdx.x * blockDim.x + threadIdx.x;
    if (idx >= BB * LL * DD) return;
    int d = idx % DHH;
    int h = (idx / DHH) % HH;
    int pos = (idx / DD) % LL;
    int b = idx / (LL * DD);
    const float* base = qkv + ((size_t)b * LL + pos) * 3 * DD;
    float qv = base[h * DHH + d];
    float kv = base[DD + h * DHH + d];
    float vv = base[2 * DD + h * DHH + d];
    int i = d & 31;
    double ang = (double)pos * exp(-((double)(2 * i) / 64.0) * 9.210340371976184);
    float c = (float)cos(ang);
    float sn = (float)sin(ang);
    float qr, kr;
    if (d < 32) {
        float q2 = base[h * DHH + d + 32];
        float k2 = base[DD + h * DHH + d + 32];
        qr = qv * c - q2 * sn;
        kr = kv * c - k2 * sn;
    } else {
        float q2 = base[h * DHH + d - 32];
        float k2 = base[DD + h * DHH + d - 32];
        qr = qv * c + q2 * sn;
        kr = kv * c + k2 * sn;
    }
    size_t o = (((size_t)b * HH + h) * LL + pos) * DHH + d;
    qo[o] = qr; ko[o] = kr; vo[o] = vv;
}

// ---------------- windowed attention (flash-style, fp32) ----------------
__global__ void attn_kernel(const float* __restrict__ q, const float* __restrict__ k,
                            const float* __restrict__ v, const float* __restrict__ biasb,
                            float* __restrict__ y) {
    const int q0 = blockIdx.x * 64;
    const int h = blockIdx.y;
    const int b = blockIdx.z;
    const int tid = threadIdx.x;
    const int ty = tid >> 2;   // q row in tile 0..63
    const int tx = tid & 3;    // dim quarter
    const int lane = tid & 31;

    __shared__ __align__(16) float Ks[64][64];
    __shared__ __align__(16) float Vs[64][64];

    const int qi = q0 + ty;
    const float* qrow = q + ((((size_t)b * HH + h) * LL) + qi) * DHH + tx * 16;
    float qf[16];
#pragma unroll
    for (int i = 0; i < 16; i++) qf[i] = qrow[i];

    float o[16];
#pragma unroll
    for (int i = 0; i < 16; i++) o[i] = 0.f;
    float mrun = -3.0e38f;
    float lsum = 0.f;
    const float scale = 0.125f;  // 1/sqrt(64)

    int jstart = q0 - WIN; if (jstart < 0) jstart = 0;
    int jend = q0 + 64 + WIN; if (jend > LL) jend = LL;

    const float* kbase = k + (((size_t)b * HH + h) * LL) * DHH;
    const float* vbase = v + (((size_t)b * HH + h) * LL) * DHH;
    const float* brow = biasb + ((size_t)b * LL + qi) * BW + (WIN - qi);

    for (int j0 = jstart; j0 < jend; j0 += 64) {
        __syncthreads();
        {
            int r = tid >> 2;
            int c = (tid & 3) * 16;
            const float4* ks = (const float4*)(kbase + (size_t)(j0 + r) * DHH + c);
            const float4* vs = (const float4*)(vbase + (size_t)(j0 + r) * DHH + c);
            float4* kd = (float4*)(&Ks[r][c]);
            float4* vd = (float4*)(&Vs[r][c]);
#pragma unroll
            for (int i = 0; i < 4; i++) { kd[i] = ks[i]; vd[i] = vs[i]; }
        }
        __syncthreads();

        float sloc[16];
#pragma unroll
        for (int jj = 0; jj < 64; jj++) {
            float part = 0.f;
            const float* kr = &Ks[jj][tx * 16];
#pragma unroll
            for (int i = 0; i < 16; i++) part = fmaf(qf[i], kr[i], part);
            part += __shfl_xor_sync(0xffffffffu, part, 1);
            part += __shfl_xor_sync(0xffffffffu, part, 2);
            if ((jj & 3) == tx) {
                int j = j0 + jj;
                int dist = j - qi; if (dist < 0) dist = -dist;
                float sv;
                if (dist <= WIN) sv = part * scale + brow[j];
                else sv = -3.0e38f;
                sloc[jj >> 2] = sv;
            }
        }
        float tmax = -3.0e38f;
#pragma unroll
        for (int i = 0; i < 16; i++) tmax = fmaxf(tmax, sloc[i]);
        tmax = fmaxf(tmax, __shfl_xor_sync(0xffffffffu, tmax, 1));
        tmax = fmaxf(tmax, __shfl_xor_sync(0xffffffffu, tmax, 2));
        float mnew = fmaxf(mrun, tmax);
        float fac = __expf(mrun - mnew);
        mrun = mnew;
        lsum *= fac;
#pragma unroll
        for (int i = 0; i < 16; i++) o[i] *= fac;
        float pl[16];
#pragma unroll
        for (int i = 0; i < 16; i++) {
            float pv = __expf(sloc[i] - mnew);
            pv = (sloc[i] < -1.0e30f) ? 0.f : pv;
            pl[i] = pv;
            lsum += pv;
        }
#pragma unroll
        for (int jj = 0; jj < 64; jj++) {
            float pv = __shfl_sync(0xffffffffu, pl[jj >> 2], (lane & ~3) | (jj & 3));
            const float* vr = &Vs[jj][tx * 16];
#pragma unroll
            for (int i = 0; i < 16; i++) o[i] = fmaf(pv, vr[i], o[i]);
        }
    }
    lsum += __shfl_xor_sync(0xffffffffu, lsum, 1);
    lsum += __shfl_xor_sync(0xffffffffu, lsum, 2);
    float inv = 1.0f / lsum;
    float* yout = y + ((size_t)b * LL + qi) * DD + h * DHH + tx * 16;
#pragma unroll
    for (int i = 0; i < 16; i++) yout[i] = o[i] * inv;
}

// ---------------- driver ----------------
extern "C" void kernel_launch(void* const* d_in, const int* in_sizes, int n_in,
                              void* d_out, int out_size) {
    const float* s_in  = (const float*)d_in[0];
    const float* pair  = (const float*)d_in[1];
    const float* qkv_w = (const float*)d_in[2];
    const float* qkv_b = (const float*)d_in[3];
    const float* out_w = (const float*)d_in[4];
    const float* out_b = (const float*)d_in[5];
    const float* fc1_w = (const float*)d_in[6];
    const float* fc1_b = (const float*)d_in[7];
    const float* fc2_w = (const float*)d_in[8];
    const float* fc2_b = (const float*)d_in[9];
    const float* ln_g  = (const float*)d_in[10];
    const float* ln_b  = (const float*)d_in[11];
    const float* pb_w  = (const float*)d_in[12];
    const float* pb_b  = (const float*)d_in[13];
    float* s = (float*)d_out;

    float *p_h, *p_qkv, *p_q, *p_k, *p_v, *p_y, *p_u, *p_bias;
    cudaGetSymbolAddress((void**)&p_h, g_h);
    cudaGetSymbolAddress((void**)&p_qkv, g_qkv);
    cudaGetSymbolAddress((void**)&p_q, g_q);
    cudaGetSymbolAddress((void**)&p_k, g_k);
    cudaGetSymbolAddress((void**)&p_v, g_v);
    cudaGetSymbolAddress((void**)&p_y, g_y);
    cudaGetSymbolAddress((void**)&p_u, g_u);
    cudaGetSymbolAddress((void**)&p_bias, g_bias);

    cudaMemcpyAsync(s, s_in, sizeof(float) * BB * LL * DD, cudaMemcpyDeviceToDevice, 0);

    {
        int nwarps = BB * LL * 257;
        int blocks = (nwarps * 32 + 255) / 256;
        bias_kernel<<<blocks, 256>>>(pair, ln_g, ln_b, pb_w, pb_b, p_bias);
    }

    const int NROWS = BB * LL;  // 2048
    for (int l = 0; l < NLAYER; l++) {
        rmsnorm_kernel<<<NROWS, 256>>>(s, p_h);
        gemm_kernel<0, 0><<<dim3(3 * DD / 64, NROWS / 128), 256>>>(
            p_h, qkv_w + (size_t)l * 3 * DD * DD, qkv_b + (size_t)l * 3 * DD, p_qkv, DD, 3 * DD);
        rope_kernel<<<(BB * LL * DD + 255) / 256, 256>>>(p_qkv, p_q, p_k, p_v);
        attn_kernel<<<dim3(LL / 64, HH, BB), 256>>>(
            p_q, p_k, p_v, p_bias + (size_t)l * BB * LL * BW, p_y);
        gemm_kernel<0, 1><<<dim3(DD / 64, NROWS / 128), 256>>>(
            p_y, out_w + (size_t)l * DD * DD, out_b + (size_t)l * DD, s, DD, DD);
        rmsnorm_kernel<<<NROWS, 256>>>(s, p_h);
        gemm_kernel<1, 0><<<dim3(MLPD / 64, NROWS / 128), 256>>>(
            p_h, fc1_w + (size_t)l * MLPD * DD, fc1_b + (size_t)l * MLPD, p_u, DD, MLPD);
        gemm_kernel<0, 1><<<dim3(DD / 64, NROWS / 128), 256>>>(
            p_u, fc2_w + (size_t)l * DD * MLPD, fc2_b + (size_t)l * DD, s, MLPD, DD);
    }
}

// round 3
// speedup vs baseline: 1.3081x; 1.3081x over previous
#include <cuda_runtime.h>
#include <math.h>
#include <stdint.h>

#define BB 2
#define LL 1024
#define DD 768
#define HH 12
#define DHH 64
#define DP 32
#define MLPD 3072
#define NLAYER 4
#define WIN 128
#define BW 264
#define EPS_RMS 1.1920929e-07f
#define EPS_LN 1e-5f

// ---------------- scratch ----------------
__device__ float g_h[BB * LL * DD];
__device__ float g_qkv[BB * LL * 3 * DD];
__device__ float g_q[BB * HH * LL * DHH];
__device__ float g_k[BB * HH * LL * DHH];
__device__ float g_v[BB * HH * LL * DHH];
__device__ float g_y[BB * LL * DD];
__device__ float g_u[BB * LL * MLPD];
__device__ float g_bias[NLAYER * BB * LL * BW];
__device__ float g_cos[LL * 32];
__device__ float g_sin[LL * 32];

// ---------------- helpers ----------------
__device__ __forceinline__ float warp_sum(float v) {
#pragma unroll
    for (int o = 16; o; o >>= 1) v += __shfl_xor_sync(0xffffffffu, v, o);
    return v;
}
__device__ __forceinline__ float gelu_f(float x) {
    return 0.5f * x * (1.0f + erff(x * 0.70710678118654752f));
}
__device__ __forceinline__ uint32_t f2tf32(float x) {
    uint32_t r;
    asm("cvt.rna.tf32.f32 %0, %1;" : "=r"(r) : "f"(x));
    return r;
}

#define MMA_TF32(d, a, b0, b1)                                                       \
    asm volatile(                                                                    \
        "mma.sync.aligned.m16n8k8.row.col.f32.tf32.tf32.f32 "                        \
        "{%0,%1,%2,%3},{%4,%5,%6,%7},{%8,%9},{%0,%1,%2,%3};"                         \
        : "+f"(d[0]), "+f"(d[1]), "+f"(d[2]), "+f"(d[3])                             \
        : "r"(a[0]), "r"(a[1]), "r"(a[2]), "r"(a[3]), "r"(b0), "r"(b1))

// ---------------- rope table (fp64 once) ----------------
__global__ void rope_table_kernel() {
    int idx = blockIdx.x * blockDim.x + threadIdx.x;
    if (idx >= LL * 32) return;
    int i = idx & 31;
    int pos = idx >> 5;
    double invf = exp(-((double)(2 * i) / 64.0) * 9.210340371976184);
    double ang = (double)pos * invf;
    g_cos[idx] = (float)cos(ang);
    g_sin[idx] = (float)sin(ang);
}

// ---------------- pair-bias (all layers, windowed) ----------------
__global__ void bias_kernel(const float* __restrict__ pair,
                            const float* __restrict__ ln_g, const float* __restrict__ ln_b,
                            const float* __restrict__ pb_w, const float* __restrict__ pb_b,
                            float* __restrict__ bout) {
    const int WN = 2 * WIN + 1;
    int gw = (blockIdx.x * blockDim.x + threadIdx.x) >> 5;
    int lane = threadIdx.x & 31;
    int total = BB * LL * WN;
    if (gw >= total) return;
    int w = gw % WN;
    int t = gw / WN;
    int qq = t % LL;
    int b = t / LL;
    int j = qq - WIN + w;
    if (j < 0 || j >= LL) return;

    float x = pair[(((size_t)b * LL + qq) * LL + j) * DP + lane];
    float m = warp_sum(x) * (1.0f / 32.0f);
    float d = x - m;
    float var = warp_sum(d * d) * (1.0f / 32.0f);
    float nm = d * rsqrtf(var + EPS_LN);
#pragma unroll
    for (int l = 0; l < NLAYER; l++) {
        float wv = pb_w[l * DP + lane];
        float contrib = (nm * ln_g[l * DP + lane] + ln_b[l * DP + lane]) * wv;
        float sum = warp_sum(contrib);
        if (lane == 0)
            bout[(((size_t)l * BB + b) * LL + qq) * BW + w] = sum + pb_b[l];
    }
}

// ---------------- rmsnorm ----------------
__global__ void rmsnorm_kernel(const float* __restrict__ s, float* __restrict__ h) {
    __shared__ float red[8];
    __shared__ float s_inv;
    int row = blockIdx.x;
    int tid = threadIdx.x;
    const float* x = s + (size_t)row * DD;
    float v0 = x[tid], v1 = x[tid + 256], v2 = x[tid + 512];
    float ss = v0 * v0 + v1 * v1 + v2 * v2;
    ss = warp_sum(ss);
    if ((tid & 31) == 0) red[tid >> 5] = ss;
    __syncthreads();
    if (tid == 0) {
        float t = 0.f;
#pragma unroll
        for (int i = 0; i < 8; i++) t += red[i];
        s_inv = rsqrtf(t * (1.0f / (float)DD) + EPS_RMS);
    }
    __syncthreads();
    float inv = s_inv;
    float* ho = h + (size_t)row * DD;
    ho[tid] = v0 * inv; ho[tid + 256] = v1 * inv; ho[tid + 512] = v2 * inv;
}

// ---------------- tensor-core GEMM (3xTF32): out[N,M] = A @ W^T + bias ----------------
// BN fixed at 128. BM in {64,128}. blockDim = BM*2 threads.
template <int BM, int ACT, int RESID>
__global__ void __launch_bounds__(BM * 2) gemm_tc(
    const float* __restrict__ A, const float* __restrict__ W,
    const float* __restrict__ bias, float* __restrict__ out, int K, int N) {
    constexpr int T = BM * 2;
    constexpr int STR = 20;  // stride in floats; (20g+tg) mod 32 all-distinct -> conflict-free
    __shared__ uint32_t As_h[BM][STR], As_l[BM][STR];
    __shared__ uint32_t Ws_h[128][STR], Ws_l[128][STR];

    const int tid = threadIdx.x;
    const int lane = tid & 31;
    const int w = tid >> 5;
    const int wm = w >> 1;
    const int wn = w & 1;
    const int g = lane >> 2;
    const int tg = lane & 3;
    const int row0 = blockIdx.y * BM;
    const int col0 = blockIdx.x * 128;

    float acc[2][8][4];
#pragma unroll
    for (int a = 0; a < 2; a++)
#pragma unroll
        for (int b = 0; b < 8; b++)
#pragma unroll
            for (int c = 0; c < 4; c++) acc[a][b][c] = 0.f;

    for (int k0 = 0; k0 < K; k0 += 16) {
        __syncthreads();
#pragma unroll
        for (int e = tid; e < BM * 4; e += T) {
            int m = e >> 2, kq = (e & 3) * 4;
            float4 v = *(const float4*)(A + (size_t)(row0 + m) * K + k0 + kq);
            float vv[4] = {v.x, v.y, v.z, v.w};
#pragma unroll
            for (int i = 0; i < 4; i++) {
                uint32_t h = f2tf32(vv[i]);
                As_h[m][kq + i] = h;
                As_l[m][kq + i] = f2tf32(vv[i] - __uint_as_float(h));
            }
        }
#pragma unroll
        for (int e = tid; e < 512; e += T) {
            int n = e >> 2, kq = (e & 3) * 4;
            float4 v = *(const float4*)(W + (size_t)(col0 + n) * K + k0 + kq);
            float vv[4] = {v.x, v.y, v.z, v.w};
#pragma unroll
            for (int i = 0; i < 4; i++) {
                uint32_t h = f2tf32(vv[i]);
                Ws_h[n][kq + i] = h;
                Ws_l[n][kq + i] = f2tf32(vv[i] - __uint_as_float(h));
            }
        }
        __syncthreads();
#pragma unroll
        for (int kk = 0; kk < 16; kk += 8) {
            uint32_t ah[2][4], al[2][4];
#pragma unroll
            for (int mt = 0; mt < 2; mt++) {
                int r = wm * 32 + mt * 16 + g;
                ah[mt][0] = As_h[r][kk + tg];
                ah[mt][1] = As_h[r + 8][kk + tg];
                ah[mt][2] = As_h[r][kk + tg + 4];
                ah[mt][3] = As_h[r + 8][kk + tg + 4];
                al[mt][0] = As_l[r][kk + tg];
                al[mt][1] = As_l[r + 8][kk + tg];
                al[mt][2] = As_l[r][kk + tg + 4];
                al[mt][3] = As_l[r + 8][kk + tg + 4];
            }
#pragma unroll
            for (int nt = 0; nt < 8; nt++) {
                int c = wn * 64 + nt * 8 + g;
                uint32_t bh0 = Ws_h[c][kk + tg];
                uint32_t bh1 = Ws_h[c][kk + tg + 4];
                uint32_t bl0 = Ws_l[c][kk + tg];
                uint32_t bl1 = Ws_l[c][kk + tg + 4];
#pragma unroll
                for (int mt = 0; mt < 2; mt++) {
                    MMA_TF32(acc[mt][nt], ah[mt], bh0, bh1);
                    MMA_TF32(acc[mt][nt], al[mt], bh0, bh1);
                    MMA_TF32(acc[mt][nt], ah[mt], bl0, bl1);
                }
            }
        }
    }

#pragma unroll
    for (int mt = 0; mt < 2; mt++) {
#pragma unroll
        for (int nt = 0; nt < 8; nt++) {
            int col = col0 + wn * 64 + nt * 8 + tg * 2;
            float b0 = bias[col], b1 = bias[col + 1];
#pragma unroll
            for (int half = 0; half < 2; half++) {
                int row = row0 + wm * 32 + mt * 16 + g + half * 8;
                float v0 = acc[mt][nt][half * 2] + b0;
                float v1 = acc[mt][nt][half * 2 + 1] + b1;
                if (ACT == 1) { v0 = gelu_f(v0); v1 = gelu_f(v1); }
                float* op = out + (size_t)row * N + col;
                if (RESID) { v0 += op[0]; v1 += op[1]; }
                op[0] = v0; op[1] = v1;
            }
        }
    }
}

// ---------------- RoPE (table-based) + layout [B,L,3D] -> [B,H,L,DH] ----------------
__global__ void rope_kernel(const float* __restrict__ qkv, float* __restrict__ qo,
                            float* __restrict__ ko, float* __restrict__ vo) {
    int idx = blockIdx.x * blockDim.x + threadIdx.x;
    if (idx >= BB * LL * DD) return;
    int d = idx % DHH;
    int h = (idx / DHH) % HH;
    int pos = (idx / DD) % LL;
    int b = idx / (LL * DD);
    const float* base = qkv + ((size_t)b * LL + pos) * 3 * DD;
    float qv = base[h * DHH + d];
    float kv = base[DD + h * DHH + d];
    float vv = base[2 * DD + h * DHH + d];
    int i = d & 31;
    float c = g_cos[pos * 32 + i];
    float sn = g_sin[pos * 32 + i];
    float qr, kr;
    if (d < 32) {
        float q2 = base[h * DHH + d + 32];
        float k2 = base[DD + h * DHH + d + 32];
        qr = qv * c - q2 * sn;
        kr = kv * c - k2 * sn;
    } else {
        float q2 = base[h * DHH + d - 32];
        float k2 = base[DD + h * DHH + d - 32];
        qr = qv * c + q2 * sn;
        kr = kv * c + k2 * sn;
    }
    size_t o = (((size_t)b * HH + h) * LL + pos) * DHH + d;
    qo[o] = qr; ko[o] = kr; vo[o] = vv;
}

// ---------------- windowed attention (flash-style, fp32) ----------------
__global__ void attn_kernel(const float* __restrict__ q, const float* __restrict__ k,
                            const float* __restrict__ v, const float* __restrict__ biasb,
                            float* __restrict__ y) {
    const int q0 = blockIdx.x * 64;
    const int h = blockIdx.y;
    const int b = blockIdx.z;
    const int tid = threadIdx.x;
    const int ty = tid >> 2;
    const int tx = tid & 3;
    const int lane = tid & 31;

    __shared__ __align__(16) float Ks[64][64];
    __shared__ __align__(16) float Vs[64][64];

    const int qi = q0 + ty;
    const float* qrow = q + ((((size_t)b * HH + h) * LL) + qi) * DHH + tx * 16;
    float qf[16];
#pragma unroll
    for (int i = 0; i < 16; i++) qf[i] = qrow[i];

    float o[16];
#pragma unroll
    for (int i = 0; i < 16; i++) o[i] = 0.f;
    float mrun = -3.0e38f;
    float lsum = 0.f;
    const float scale = 0.125f;

    int jstart = q0 - WIN; if (jstart < 0) jstart = 0;
    int jend = q0 + 64 + WIN; if (jend > LL) jend = LL;

    const float* kbase = k + (((size_t)b * HH + h) * LL) * DHH;
    const float* vbase = v + (((size_t)b * HH + h) * LL) * DHH;
    const float* brow = biasb + ((size_t)b * LL + qi) * BW + (WIN - qi);

    for (int j0 = jstart; j0 < jend; j0 += 64) {
        __syncthreads();
        {
            int r = tid >> 2;
            int c = (tid & 3) * 16;
            const float4* ks = (const float4*)(kbase + (size_t)(j0 + r) * DHH + c);
            const float4* vs = (const float4*)(vbase + (size_t)(j0 + r) * DHH + c);
            float4* kd = (float4*)(&Ks[r][c]);
            float4* vd = (float4*)(&Vs[r][c]);
#pragma unroll
            for (int i = 0; i < 4; i++) { kd[i] = ks[i]; vd[i] = vs[i]; }
        }
        __syncthreads();

        float sloc[16];
#pragma unroll
        for (int jj = 0; jj < 64; jj++) {
            float part = 0.f;
            const float* kr = &Ks[jj][tx * 16];
#pragma unroll
            for (int i = 0; i < 16; i++) part = fmaf(qf[i], kr[i], part);
            part += __shfl_xor_sync(0xffffffffu, part, 1);
            part += __shfl_xor_sync(0xffffffffu, part, 2);
            if ((jj & 3) == tx) {
                int j = j0 + jj;
                int dist = j - qi; if (dist < 0) dist = -dist;
                float sv;
                if (dist <= WIN) sv = part * scale + brow[j];
                else sv = -3.0e38f;
                sloc[jj >> 2] = sv;
            }
        }
        float tmax = -3.0e38f;
#pragma unroll
        for (int i = 0; i < 16; i++) tmax = fmaxf(tmax, sloc[i]);
        tmax = fmaxf(tmax, __shfl_xor_sync(0xffffffffu, tmax, 1));
        tmax = fmaxf(tmax, __shfl_xor_sync(0xffffffffu, tmax, 2));
        float mnew = fmaxf(mrun, tmax);
        float fac = __expf(mrun - mnew);
        mrun = mnew;
        lsum *= fac;
#pragma unroll
        for (int i = 0; i < 16; i++) o[i] *= fac;
        float pl[16];
#pragma unroll
        for (int i = 0; i < 16; i++) {
            float pv = __expf(sloc[i] - mnew);
            pv = (sloc[i] < -1.0e30f) ? 0.f : pv;
            pl[i] = pv;
            lsum += pv;
        }
#pragma unroll
        for (int jj = 0; jj < 64; jj++) {
            float pv = __shfl_sync(0xffffffffu, pl[jj >> 2], (lane & ~3) | (jj & 3));
            const float* vr = &Vs[jj][tx * 16];
#pragma unroll
            for (int i = 0; i < 16; i++) o[i] = fmaf(pv, vr[i], o[i]);
        }
    }
    lsum += __shfl_xor_sync(0xffffffffu, lsum, 1);
    lsum += __shfl_xor_sync(0xffffffffu, lsum, 2);
    float inv = 1.0f / lsum;
    float* yout = y + ((size_t)b * LL + qi) * DD + h * DHH + tx * 16;
#pragma unroll
    for (int i = 0; i < 16; i++) yout[i] = o[i] * inv;
}

// ---------------- driver ----------------
extern "C" void kernel_launch(void* const* d_in, const int* in_sizes, int n_in,
                              void* d_out, int out_size) {
    const float* s_in  = (const float*)d_in[0];
    const float* pair  = (const float*)d_in[1];
    const float* qkv_w = (const float*)d_in[2];
    const float* qkv_b = (const float*)d_in[3];
    const float* out_w = (const float*)d_in[4];
    const float* out_b = (const float*)d_in[5];
    const float* fc1_w = (const float*)d_in[6];
    const float* fc1_b = (const float*)d_in[7];
    const float* fc2_w = (const float*)d_in[8];
    const float* fc2_b = (const float*)d_in[9];
    const float* ln_g  = (const float*)d_in[10];
    const float* ln_b  = (const float*)d_in[11];
    const float* pb_w  = (const float*)d_in[12];
    const float* pb_b  = (const float*)d_in[13];
    float* s = (float*)d_out;

    float *p_h, *p_qkv, *p_q, *p_k, *p_v, *p_y, *p_u, *p_bias;
    cudaGetSymbolAddress((void**)&p_h, g_h);
    cudaGetSymbolAddress((void**)&p_qkv, g_qkv);
    cudaGetSymbolAddress((void**)&p_q, g_q);
    cudaGetSymbolAddress((void**)&p_k, g_k);
    cudaGetSymbolAddress((void**)&p_v, g_v);
    cudaGetSymbolAddress((void**)&p_y, g_y);
    cudaGetSymbolAddress((void**)&p_u, g_u);
    cudaGetSymbolAddress((void**)&p_bias, g_bias);

    cudaMemcpyAsync(s, s_in, sizeof(float) * BB * LL * DD, cudaMemcpyDeviceToDevice, 0);

    rope_table_kernel<<<(LL * 32 + 255) / 256, 256>>>();

    {
        int nwarps = BB * LL * 257;
        int blocks = (nwarps * 32 + 255) / 256;
        bias_kernel<<<blocks, 256>>>(pair, ln_g, ln_b, pb_w, pb_b, p_bias);
    }

    const int NROWS = BB * LL;
    for (int l = 0; l < NLAYER; l++) {
        rmsnorm_kernel<<<NROWS, 256>>>(s, p_h);
        gemm_tc<128, 0, 0><<<dim3(3 * DD / 128, NROWS / 128), 256>>>(
            p_h, qkv_w + (size_t)l * 3 * DD * DD, qkv_b + (size_t)l * 3 * DD, p_qkv, DD, 3 * DD);
        rope_kernel<<<(BB * LL * DD + 255) / 256, 256>>>(p_qkv, p_q, p_k, p_v);
        attn_kernel<<<dim3(LL / 64, HH, BB), 256>>>(
            p_q, p_k, p_v, p_bias + (size_t)l * BB * LL * BW, p_y);
        gemm_tc<64, 0, 1><<<dim3(DD / 128, NROWS / 64), 128>>>(
            p_y, out_w + (size_t)l * DD * DD, out_b + (size_t)l * DD, s, DD, DD);
        rmsnorm_kernel<<<NROWS, 256>>>(s, p_h);
        gemm_tc<128, 1, 0><<<dim3(MLPD / 128, NROWS / 128), 256>>>(
            p_h, fc1_w + (size_t)l * MLPD * DD, fc1_b + (size_t)l * MLPD, p_u, DD, MLPD);
        gemm_tc<64, 0, 1><<<dim3(DD / 128, NROWS / 64), 128>>>(
            p_u, fc2_w + (size_t)l * DD * MLPD, fc2_b + (size_t)l * DD, s, MLPD, DD);
    }
}